// round 1
// baseline (speedup 1.0000x reference)
#include <cuda_runtime.h>
#include <cstdint>
#include <cstddef>

// ---------------------------------------------------------------------------
// Problem constants (fixed by setup_inputs)
// ---------------------------------------------------------------------------
#define B_     8
#define IN_CH  16
#define OUT_CH 32
#define GFC    64
#define EH     256
#define EW     320
#define OH     128   // EH/2
#define OW     160   // EW/2
#define EY2    0
#define EX2    64
#define HFULL2 256   // prev_h rows
#define WFULL2 320   // prev_h cols

// Output layout: hidden | new_h | new_c | new_gf
#define N_HID  ((size_t)B_*OUT_CH*OH*OW)            // 5,242,880
#define N_HC   ((size_t)B_*OUT_CH*HFULL2*WFULL2)    // 20,971,520
#define OFF_H  (N_HID)
#define OFF_C  (N_HID + N_HC)
#define OFF_GF (N_HID + 2*N_HC)

// ---------------------------------------------------------------------------
// Scratch (static device globals — no allocation at runtime)
// ---------------------------------------------------------------------------
__device__ float g_xfeat[B_*OUT_CH*OH*OW];           // 21 MB
__device__ float g_gates[B_*4*OUT_CH*OH*OW];         // 84 MB
__device__ float g_gfsum[B_*GFC];
__device__ float g_gfc[B_*96*4];                     // gf conv contribution, 4 edge variants

__device__ __forceinline__ float sigf(float x) { return 1.0f / (1.0f + expf(-x)); }

// ---------------------------------------------------------------------------
// Kernel A: precompute gf-broadcast conv contributions + zero gf accumulators
//   variant v: bit1 = missing top kernel row (oy==0), bit0 = missing left col
// ---------------------------------------------------------------------------
__global__ void prep_kernel(const float* __restrict__ gf, const float* __restrict__ w) {
    int idx = blockIdx.x * 256 + threadIdx.x;
    if (idx < B_*GFC) g_gfsum[idx] = 0.0f;
    if (idx >= B_*96*4) return;
    int v  = idx & 3;
    int oc = (idx >> 2) % 96;
    int b  = idx / (96*4);
    int ky0 = (v >> 1) & 1, kx0 = v & 1;
    float s = 0.0f;
    for (int c = 0; c < GFC; c++) {
        const float* wp = w + ((size_t)(oc*80) + IN_CH + c) * 9;
        float wsum = 0.0f;
        for (int ky = ky0; ky < 3; ky++)
            for (int kx = kx0; kx < 3; kx++)
                wsum += wp[ky*3 + kx];
        s += gf[b*GFC + c] * wsum;
    }
    g_gfc[idx] = s;
}

// ---------------------------------------------------------------------------
// Kernel B: conv1 (stride 2, pad 1, real channels 0..15) + gf contrib + bias
//           + tanh; oc tile 0 -> store x_feat; oc tiles 1,2 -> mean reduce.
// Grid: (160 tiles, 3 oc-tiles, 8 batch), 256 threads.
// Thread t: lane = pixel slot (x4 pixels strided 32), warp = oc slot (x4 oc strided 8)
// ---------------------------------------------------------------------------
__global__ __launch_bounds__(256) void conv1_kernel(
    const float* __restrict__ x, const float* __restrict__ w,
    const float* __restrict__ bias)
{
    __shared__ float in_s[17*33];
    __shared__ float w_s[32*9];

    const int tile = blockIdx.x;
    const int tx = tile % 10, ty = tile / 10;
    const int ocb = blockIdx.y * 32;
    const int b = blockIdx.z;
    const int t = threadIdx.x;
    const int lane = t & 31, warp = t >> 5;
    const int oy0 = ty * 8, ox0 = tx * 16;

    float acc[4][4];
    #pragma unroll
    for (int i = 0; i < 4; i++)
        #pragma unroll
        for (int j = 0; j < 4; j++) acc[i][j] = 0.0f;

    const float* xb = x + (size_t)b * IN_CH * EH * EW;

    for (int ic = 0; ic < IN_CH; ic++) {
        __syncthreads();
        for (int i = t; i < 17*33; i += 256) {
            int liy = i / 33, lix = i % 33;
            int gy = 2*oy0 - 1 + liy, gx = 2*ox0 - 1 + lix;
            float v = 0.0f;
            if ((unsigned)gy < EH && (unsigned)gx < EW)
                v = xb[((size_t)ic*EH + gy)*EW + gx];
            in_s[i] = v;
        }
        for (int i = t; i < 32*9; i += 256) {
            int oc = i / 9, k = i % 9;
            w_s[i] = w[((size_t)(ocb + oc)*80 + ic)*9 + k];
        }
        __syncthreads();

        float wr[4][9];
        #pragma unroll
        for (int j = 0; j < 4; j++)
            #pragma unroll
            for (int k = 0; k < 9; k++)
                wr[j][k] = w_s[(warp + 8*j)*9 + k];

        #pragma unroll
        for (int i = 0; i < 4; i++) {
            int p = lane + 32*i;
            int py = p >> 4, px = p & 15;
            float vin[9];
            #pragma unroll
            for (int ky = 0; ky < 3; ky++)
                #pragma unroll
                for (int kx = 0; kx < 3; kx++)
                    vin[ky*3+kx] = in_s[(2*py + ky)*33 + 2*px + kx];
            #pragma unroll
            for (int j = 0; j < 4; j++) {
                float a = acc[i][j];
                #pragma unroll
                for (int k = 0; k < 9; k++) a += vin[k] * wr[j][k];
                acc[i][j] = a;
            }
        }
    }

    // Epilogue
    if (ocb == 0) {
        #pragma unroll
        for (int i = 0; i < 4; i++) {
            int p = lane + 32*i;
            int py = p >> 4, px = p & 15;
            int gy = oy0 + py, gx = ox0 + px;
            int v = ((gy == 0) ? 2 : 0) | ((gx == 0) ? 1 : 0);
            #pragma unroll
            for (int j = 0; j < 4; j++) {
                int oc = warp + 8*j;
                float val = tanhf(acc[i][j] + bias[oc] + g_gfc[(b*96 + oc)*4 + v]);
                g_xfeat[(((size_t)b*OUT_CH + oc)*OH + gy)*OW + gx] = val;
            }
        }
    } else {
        float psum[4] = {0.0f, 0.0f, 0.0f, 0.0f};
        #pragma unroll
        for (int i = 0; i < 4; i++) {
            int p = lane + 32*i;
            int py = p >> 4, px = p & 15;
            int gy = oy0 + py, gx = ox0 + px;
            int v = ((gy == 0) ? 2 : 0) | ((gx == 0) ? 1 : 0);
            #pragma unroll
            for (int j = 0; j < 4; j++) {
                int oc = ocb + warp + 8*j;
                psum[j] += tanhf(acc[i][j] + bias[oc] + g_gfc[(b*96 + oc)*4 + v]);
            }
        }
        #pragma unroll
        for (int j = 0; j < 4; j++) {
            float s = psum[j];
            #pragma unroll
            for (int off = 16; off > 0; off >>= 1)
                s += __shfl_xor_sync(0xFFFFFFFFu, s, off);
            if (lane == 0) {
                int g = (ocb + warp + 8*j) - OUT_CH;   // gf channel index
                atomicAdd(&g_gfsum[b*GFC + g], s);
            }
        }
    }
}

// ---------------------------------------------------------------------------
// Kernel C: new_gf = tanh(gf + mean)
// ---------------------------------------------------------------------------
__global__ void gf_kernel(const float* __restrict__ gf, float* __restrict__ out) {
    int i = threadIdx.x;   // 512 = B_*GFC
    out[OFF_GF + i] = tanhf(gf[i] + g_gfsum[i] * (1.0f / (float)(OH*OW)));
}

// ---------------------------------------------------------------------------
// Kernel D: gates conv (stride 1, 64 -> 128 ch over 128x160), store to g_gates
// ic 0..31: x_feat zero-padded; ic 32..63: prev_h window [iy-1, 63+ix] (iy==0 -> 0)
// Grid: (160 tiles, 4 oc-tiles, 8 batch), 256 threads.
// ---------------------------------------------------------------------------
__global__ __launch_bounds__(256) void conv2_kernel(
    const float* __restrict__ prev_h, const float* __restrict__ w,
    const float* __restrict__ bias)
{
    __shared__ float in_s[10*18];
    __shared__ float w_s[32*9];

    const int tile = blockIdx.x;
    const int tx = tile % 10, ty = tile / 10;
    const int ocb = blockIdx.y * 32;
    const int b = blockIdx.z;
    const int t = threadIdx.x;
    const int lane = t & 31, warp = t >> 5;
    const int oy0 = ty * 8, ox0 = tx * 16;

    float acc[4][4];
    #pragma unroll
    for (int i = 0; i < 4; i++)
        #pragma unroll
        for (int j = 0; j < 4; j++) acc[i][j] = 0.0f;

    for (int ic = 0; ic < 2*OUT_CH; ic++) {
        __syncthreads();
        if (t < 10*18) {
            int liy = t / 18, lix = t % 18;
            int iy = oy0 + liy, ix = ox0 + lix;   // padded-input coordinates
            float v = 0.0f;
            if (ic < OUT_CH) {
                int r = iy - 1, c = ix - 1;
                if ((unsigned)r < OH && (unsigned)c < OW)
                    v = g_xfeat[(((size_t)b*OUT_CH + ic)*OH + r)*OW + c];
            } else {
                if (iy > 0)
                    v = prev_h[(((size_t)b*OUT_CH + (ic - OUT_CH))*HFULL2 + (iy - 1))*WFULL2
                               + (EX2 - 1) + ix];
            }
            in_s[t] = v;
        }
        for (int i = t; i < 32*9; i += 256) {
            int oc = i / 9, k = i % 9;
            w_s[i] = w[((size_t)(ocb + oc)*(2*OUT_CH) + ic)*9 + k];
        }
        __syncthreads();

        float wr[4][9];
        #pragma unroll
        for (int j = 0; j < 4; j++)
            #pragma unroll
            for (int k = 0; k < 9; k++)
                wr[j][k] = w_s[(warp + 8*j)*9 + k];

        #pragma unroll
        for (int i = 0; i < 4; i++) {
            int p = lane + 32*i;
            int py = p >> 4, px = p & 15;
            float vin[9];
            #pragma unroll
            for (int ky = 0; ky < 3; ky++)
                #pragma unroll
                for (int kx = 0; kx < 3; kx++)
                    vin[ky*3+kx] = in_s[(py + ky)*18 + px + kx];
            #pragma unroll
            for (int j = 0; j < 4; j++) {
                float a = acc[i][j];
                #pragma unroll
                for (int k = 0; k < 9; k++) a += vin[k] * wr[j][k];
                acc[i][j] = a;
            }
        }
    }

    #pragma unroll
    for (int i = 0; i < 4; i++) {
        int p = lane + 32*i;
        int py = p >> 4, px = p & 15;
        int gy = oy0 + py, gx = ox0 + px;
        #pragma unroll
        for (int j = 0; j < 4; j++) {
            int oc = ocb + warp + 8*j;
            g_gates[(((size_t)b*128 + oc)*OH + gy)*OW + gx] = acc[i][j] + bias[oc];
        }
    }
}

// ---------------------------------------------------------------------------
// Kernel E: LSTM gate math + hidden/new_h/new_c region writes
// ---------------------------------------------------------------------------
__global__ void lstm_kernel(const float* __restrict__ prev_c, float* __restrict__ out) {
    size_t idx = (size_t)blockIdx.x * 256 + threadIdx.x;
    if (idx >= N_HID) return;
    int ox = (int)(idx % OW);
    size_t tmp = idx / OW;
    int oy = (int)(tmp % OH);  tmp /= OH;
    int oc = (int)(tmp % OUT_CH);
    int b  = (int)(tmp / OUT_CH);

    const size_t GSTR = (size_t)OUT_CH * OH * OW;       // gate-group channel stride
    size_t gbase = (((size_t)b*128 + oc)*OH + oy)*OW + ox;
    float ig = g_gates[gbase];
    float rg = g_gates[gbase +     GSTR];
    float og = g_gates[gbase + 2 * GSTR];
    float cg = g_gates[gbase + 3 * GSTR];

    size_t hc_idx = (((size_t)b*OUT_CH + oc)*HFULL2 + oy)*WFULL2 + EX2 + ox;
    float pc = prev_c[hc_idx];

    float cell = sigf(rg) * pc + sigf(ig) * tanhf(cg);
    float hid  = sigf(og) * tanhf(cell);

    out[idx]          = hid;    // hidden
    out[OFF_H + hc_idx] = hid;  // new_h region
    out[OFF_C + hc_idx] = cell; // new_c region
}

// ---------------------------------------------------------------------------
// Launch
// ---------------------------------------------------------------------------
extern "C" void kernel_launch(void* const* d_in, const int* in_sizes, int n_in,
                              void* d_out, int out_size) {
    const float* x       = (const float*)d_in[0];
    const float* prev_h  = (const float*)d_in[1];
    const float* prev_c  = (const float*)d_in[2];
    const float* gf      = (const float*)d_in[3];
    const float* conv_w  = (const float*)d_in[4];
    const float* conv_b  = (const float*)d_in[5];
    const float* gates_w = (const float*)d_in[6];
    const float* gates_b = (const float*)d_in[7];
    float* out = (float*)d_out;

    // gf-channel conv contributions + zero accumulators
    prep_kernel<<<(B_*96*4 + 255)/256, 256>>>(gf, conv_w);

    // conv1 + tanh + gf-mean accumulation
    conv1_kernel<<<dim3(160, 3, B_), 256>>>(x, conv_w, conv_b);

    // new_gf
    gf_kernel<<<1, B_*GFC>>>(gf, out);

    // full-tensor copies (regions overwritten by lstm_kernel afterwards)
    cudaMemcpyAsync(out + OFF_H, prev_h, N_HC * sizeof(float),
                    cudaMemcpyDeviceToDevice);
    cudaMemcpyAsync(out + OFF_C, prev_c, N_HC * sizeof(float),
                    cudaMemcpyDeviceToDevice);

    // gates conv
    conv2_kernel<<<dim3(160, 4, B_), 256>>>(prev_h, gates_w, gates_b);

    // LSTM elementwise + scatter
    lstm_kernel<<<(unsigned)((N_HID + 255)/256), 256>>>(prev_c, out);
}

// round 2
// speedup vs baseline: 1.1726x; 1.1726x over previous
#include <cuda_runtime.h>
#include <cstdint>
#include <cstddef>

// ---------------------------------------------------------------------------
// Problem constants
// ---------------------------------------------------------------------------
#define B_     8
#define IN_CH  16
#define OUT_CH 32
#define GFC    64
#define EH     256
#define EW     320
#define OH     128
#define OW     160
#define EX2    64
#define HFULL2 256
#define WFULL2 320

#define N_HID  ((size_t)B_*OUT_CH*OH*OW)
#define N_HC   ((size_t)B_*OUT_CH*HFULL2*WFULL2)
#define OFF_H  (N_HID)
#define OFF_C  (N_HID + N_HC)
#define OFF_GF (N_HID + 2*N_HC)

typedef unsigned long long ull;

__device__ float g_xfeat[B_*OUT_CH*OH*OW];
__device__ float g_gates[B_*4*OUT_CH*OH*OW];
__device__ float g_gfsum[B_*GFC];
__device__ float g_gfc[B_*96*4];

__device__ __forceinline__ float sigf(float x) { return 1.0f / (1.0f + expf(-x)); }

// f32x2 packed helpers (sm_103a: FFMA2 only reachable via PTX fma.rn.f32x2)
__device__ __forceinline__ void fma2(ull& d, ull a, ull b) {
    asm("fma.rn.f32x2 %0, %1, %2, %0;" : "+l"(d) : "l"(a), "l"(b));
}
__device__ __forceinline__ ull dup2(float v) {
    ull r; asm("mov.b64 %0, {%1, %1};" : "=l"(r) : "f"(v)); return r;
}
__device__ __forceinline__ float2 unpack2(ull p) {
    float2 f; asm("mov.b64 {%0, %1}, %2;" : "=f"(f.x), "=f"(f.y) : "l"(p)); return f;
}

// ---------------------------------------------------------------------------
// Kernel A: gf-broadcast conv contributions (4 edge variants) + zero gf sums
// ---------------------------------------------------------------------------
__global__ void prep_kernel(const float* __restrict__ gf, const float* __restrict__ w) {
    int idx = blockIdx.x * 256 + threadIdx.x;
    if (idx < B_*GFC) g_gfsum[idx] = 0.0f;
    if (idx >= B_*96*4) return;
    int v  = idx & 3;
    int oc = (idx >> 2) % 96;
    int b  = idx / (96*4);
    int ky0 = (v >> 1) & 1, kx0 = v & 1;
    float s = 0.0f;
    for (int c = 0; c < GFC; c++) {
        const float* wp = w + ((size_t)(oc*80) + IN_CH + c) * 9;
        float wsum = 0.0f;
        for (int ky = ky0; ky < 3; ky++)
            for (int kx = kx0; kx < 3; kx++)
                wsum += wp[ky*3 + kx];
        s += gf[b*GFC + c] * wsum;
    }
    g_gfc[idx] = s;
}

// ---------------------------------------------------------------------------
// Kernel B: conv1 (stride 2, pad 1, 16 real ic) + gf contrib + bias + tanh
// f32x2 packed over adjacent oc pairs. warp w -> oc = ocb + 4w + {0..3}.
// lane: 4 pixels p = lane + 32*i, py=p>>4, px=p&15 (tile 8x16).
// Grid: (160, 3, 8), 256 threads.
// ---------------------------------------------------------------------------
__global__ __launch_bounds__(256, 2) void conv1_kernel(
    const float* __restrict__ x, const float* __restrict__ w,
    const float* __restrict__ bias)
{
    __shared__ __align__(16) float in_s[2*561];   // 2 ics x 17x33
    __shared__ __align__(16) float w_s[2*288];    // 2 ics x [k*32 + oc]

    const int tile = blockIdx.x;
    const int tx = tile % 10, ty = tile / 10;
    const int ocb = blockIdx.y * 32;
    const int b = blockIdx.z;
    const int t = threadIdx.x;
    const int lane = t & 31, warp = t >> 5;
    const int oy0 = ty * 8, ox0 = tx * 16;

    ull acc[4][2] = {};
    const float* xb = x + (size_t)b * IN_CH * EH * EW;

    for (int s = 0; s < 8; s++) {
        __syncthreads();
        for (int i = t; i < 2*561; i += 256) {
            int icl = i / 561, rem = i % 561;
            int liy = rem / 33, lix = rem % 33;
            int ic = 2*s + icl;
            int gy = 2*oy0 - 1 + liy, gx = 2*ox0 - 1 + lix;
            float v = 0.0f;
            if ((unsigned)gy < EH && (unsigned)gx < EW)
                v = xb[((size_t)ic*EH + gy)*EW + gx];
            in_s[i] = v;
        }
        for (int i = t; i < 2*288; i += 256) {
            int icl = i / 288, rem = i % 288;
            int k = rem / 32, oc = rem % 32;
            w_s[i] = w[((size_t)(ocb + oc)*80 + 2*s + icl)*9 + k];
        }
        __syncthreads();

        #pragma unroll
        for (int icl = 0; icl < 2; icl++) {
            ull wr[9][2];
            const float* wp = w_s + icl*288 + 4*warp;
            #pragma unroll
            for (int k = 0; k < 9; k++) {
                wr[k][0] = *(const ull*)(wp + k*32);
                wr[k][1] = *(const ull*)(wp + k*32 + 2);
            }
            const float* ip = in_s + icl*561;
            #pragma unroll
            for (int i = 0; i < 4; i++) {
                int p = lane + 32*i;
                int py = p >> 4, px = p & 15;
                const float* q = ip + (2*py)*33 + 2*px;
                #pragma unroll
                for (int ky = 0; ky < 3; ky++) {
                    #pragma unroll
                    for (int kx = 0; kx < 3; kx++) {
                        ull dv = dup2(q[ky*33 + kx]);
                        fma2(acc[i][0], dv, wr[ky*3+kx][0]);
                        fma2(acc[i][1], dv, wr[ky*3+kx][1]);
                    }
                }
            }
        }
    }

    const int oc0 = ocb + 4*warp;
    if (ocb == 0) {
        #pragma unroll
        for (int i = 0; i < 4; i++) {
            int p = lane + 32*i;
            int py = p >> 4, px = p & 15;
            int gy = oy0 + py, gx = ox0 + px;
            int v = ((gy == 0) ? 2 : 0) | ((gx == 0) ? 1 : 0);
            float2 a0 = unpack2(acc[i][0]);
            float2 a1 = unpack2(acc[i][1]);
            float vals[4] = {a0.x, a0.y, a1.x, a1.y};
            #pragma unroll
            for (int j = 0; j < 4; j++) {
                int oc = oc0 + j;
                float val = tanhf(vals[j] + bias[oc] + g_gfc[(b*96 + oc)*4 + v]);
                g_xfeat[(((size_t)b*OUT_CH + oc)*OH + gy)*OW + gx] = val;
            }
        }
    } else {
        float psum[4] = {0.0f, 0.0f, 0.0f, 0.0f};
        #pragma unroll
        for (int i = 0; i < 4; i++) {
            int p = lane + 32*i;
            int py = p >> 4, px = p & 15;
            int gy = oy0 + py, gx = ox0 + px;
            int v = ((gy == 0) ? 2 : 0) | ((gx == 0) ? 1 : 0);
            float2 a0 = unpack2(acc[i][0]);
            float2 a1 = unpack2(acc[i][1]);
            float vals[4] = {a0.x, a0.y, a1.x, a1.y};
            #pragma unroll
            for (int j = 0; j < 4; j++) {
                int oc = oc0 + j;
                psum[j] += tanhf(vals[j] + bias[oc] + g_gfc[(b*96 + oc)*4 + v]);
            }
        }
        #pragma unroll
        for (int j = 0; j < 4; j++) {
            float sred = psum[j];
            #pragma unroll
            for (int off = 16; off > 0; off >>= 1)
                sred += __shfl_xor_sync(0xFFFFFFFFu, sred, off);
            if (lane == 0)
                atomicAdd(&g_gfsum[b*GFC + (oc0 + j - OUT_CH)], sred);
        }
    }
}

// ---------------------------------------------------------------------------
// Kernel C: new_gf
// ---------------------------------------------------------------------------
__global__ void gf_kernel(const float* __restrict__ gf, float* __restrict__ out) {
    int i = threadIdx.x;
    out[OFF_GF + i] = tanhf(gf[i] + g_gfsum[i] * (1.0f / (float)(OH*OW)));
}

// ---------------------------------------------------------------------------
// Kernel D: gates conv, f32x2 oc-pair packed, contiguous 4-pixel threads.
// Tile: 4 rows x 32 cols; warp w -> oc = ocb + 4w + {0..3}.
// lane: py = lane>>3, px0 = (lane&7)*4. Grid: (160, 4, 8), 256 threads.
// ---------------------------------------------------------------------------
__global__ __launch_bounds__(256, 2) void conv2_kernel(
    const float* __restrict__ prev_h, const float* __restrict__ gw,
    const float* __restrict__ bias)
{
    __shared__ __align__(16) float in_s[4*216];   // 4 ics x 6 rows x 36 cols
    __shared__ __align__(16) float w_s[4*288];    // 4 ics x [k*32 + oc]

    const int tile = blockIdx.x;
    const int ty = tile / 5, tx = tile % 5;
    const int ocb = blockIdx.y * 32;
    const int b = blockIdx.z;
    const int t = threadIdx.x;
    const int lane = t & 31, warp = t >> 5;
    const int oy0 = ty * 4, ox0 = tx * 32;
    const int py = lane >> 3, px0 = (lane & 7) * 4;

    ull acc[4][2] = {};

    for (int s = 0; s < 16; s++) {
        __syncthreads();
        // stage inputs (padded coords: iy in [oy0, oy0+5], ix in [ox0, ox0+35])
        for (int i = t; i < 4*216; i += 256) {
            int icl = i / 216, rem = i % 216;
            int liy = rem / 36, lix = rem % 36;
            int ic = 4*s + icl;
            int iy = oy0 + liy, ix = ox0 + lix;
            float v = 0.0f;
            if (ic < OUT_CH) {
                int r = iy - 1, c = ix - 1;
                if ((unsigned)r < OH && (unsigned)c < OW)
                    v = g_xfeat[(((size_t)b*OUT_CH + ic)*OH + r)*OW + c];
            } else {
                if (iy > 0)   // cols 63+ix < 320 always; rows iy-1 <= 128 valid
                    v = prev_h[(((size_t)b*OUT_CH + (ic - OUT_CH))*HFULL2 + (iy - 1))*WFULL2
                               + (EX2 - 1) + ix];
            }
            in_s[i] = v;
        }
        // stage weights, transposed [k][oc]
        for (int i = t; i < 4*288; i += 256) {
            int icl = i / 288, rem = i % 288;
            int k = rem / 32, oc = rem % 32;
            w_s[i] = gw[((size_t)(ocb + oc)*(2*OUT_CH) + 4*s + icl)*9 + k];
        }
        __syncthreads();

        #pragma unroll
        for (int icl = 0; icl < 4; icl++) {
            const float* ip = in_s + icl*216 + py*36 + px0;
            const float* wp = w_s + icl*288 + 4*warp;
            #pragma unroll
            for (int ky = 0; ky < 3; ky++) {
                float4 A = *(const float4*)(ip + ky*36);
                float4 Bv = *(const float4*)(ip + ky*36 + 4);
                ull d[6];
                d[0] = dup2(A.x);  d[1] = dup2(A.y);  d[2] = dup2(A.z);
                d[3] = dup2(A.w);  d[4] = dup2(Bv.x); d[5] = dup2(Bv.y);
                #pragma unroll
                for (int kx = 0; kx < 3; kx++) {
                    ull w0 = *(const ull*)(wp + (ky*3+kx)*32);
                    ull w1 = *(const ull*)(wp + (ky*3+kx)*32 + 2);
                    #pragma unroll
                    for (int pi = 0; pi < 4; pi++) {
                        fma2(acc[pi][0], d[kx+pi], w0);
                        fma2(acc[pi][1], d[kx+pi], w1);
                    }
                }
            }
        }
    }

    // epilogue: add bias, float4 stores per oc
    const int oy = oy0 + py, ox = ox0 + px0;
    #pragma unroll
    for (int q = 0; q < 2; q++) {
        int oc0 = ocb + 4*warp + 2*q;
        float b0 = bias[oc0], b1 = bias[oc0 + 1];
        float2 v0 = unpack2(acc[0][q]);
        float2 v1 = unpack2(acc[1][q]);
        float2 v2 = unpack2(acc[2][q]);
        float2 v3 = unpack2(acc[3][q]);
        float4 o0 = make_float4(v0.x + b0, v1.x + b0, v2.x + b0, v3.x + b0);
        float4 o1 = make_float4(v0.y + b1, v1.y + b1, v2.y + b1, v3.y + b1);
        *(float4*)&g_gates[(((size_t)b*128 + oc0    )*OH + oy)*OW + ox] = o0;
        *(float4*)&g_gates[(((size_t)b*128 + oc0 + 1)*OH + oy)*OW + ox] = o1;
    }
}

// ---------------------------------------------------------------------------
// Kernel E: LSTM elementwise (float4 vectorized) + region writes
// ---------------------------------------------------------------------------
__global__ void lstm_kernel(const float* __restrict__ prev_c, float* __restrict__ out) {
    size_t i4 = (size_t)blockIdx.x * 256 + threadIdx.x;   // index over float4s
    if (i4 >= N_HID/4) return;
    size_t idx = i4 * 4;
    int ox = (int)(idx % OW);
    size_t tmp = idx / OW;
    int oy = (int)(tmp % OH);  tmp /= OH;
    int oc = (int)(tmp % OUT_CH);
    int b  = (int)(tmp / OUT_CH);

    const size_t GSTR = (size_t)OUT_CH * OH * OW;
    size_t gbase = (((size_t)b*128 + oc)*OH + oy)*OW + ox;
    float4 ig = *(const float4*)&g_gates[gbase];
    float4 rg = *(const float4*)&g_gates[gbase +     GSTR];
    float4 og = *(const float4*)&g_gates[gbase + 2 * GSTR];
    float4 cg = *(const float4*)&g_gates[gbase + 3 * GSTR];

    size_t hc_idx = (((size_t)b*OUT_CH + oc)*HFULL2 + oy)*WFULL2 + EX2 + ox;
    float4 pc = *(const float4*)&prev_c[hc_idx];

    float4 cell, hid;
    cell.x = sigf(rg.x)*pc.x + sigf(ig.x)*tanhf(cg.x);
    cell.y = sigf(rg.y)*pc.y + sigf(ig.y)*tanhf(cg.y);
    cell.z = sigf(rg.z)*pc.z + sigf(ig.z)*tanhf(cg.z);
    cell.w = sigf(rg.w)*pc.w + sigf(ig.w)*tanhf(cg.w);
    hid.x = sigf(og.x)*tanhf(cell.x);
    hid.y = sigf(og.y)*tanhf(cell.y);
    hid.z = sigf(og.z)*tanhf(cell.z);
    hid.w = sigf(og.w)*tanhf(cell.w);

    *(float4*)&out[idx] = hid;
    *(float4*)&out[OFF_H + hc_idx] = hid;
    *(float4*)&out[OFF_C + hc_idx] = cell;
}

// ---------------------------------------------------------------------------
// Launch
// ---------------------------------------------------------------------------
extern "C" void kernel_launch(void* const* d_in, const int* in_sizes, int n_in,
                              void* d_out, int out_size) {
    const float* x       = (const float*)d_in[0];
    const float* prev_h  = (const float*)d_in[1];
    const float* prev_c  = (const float*)d_in[2];
    const float* gf      = (const float*)d_in[3];
    const float* conv_w  = (const float*)d_in[4];
    const float* conv_b  = (const float*)d_in[5];
    const float* gates_w = (const float*)d_in[6];
    const float* gates_b = (const float*)d_in[7];
    float* out = (float*)d_out;

    prep_kernel<<<(B_*96*4 + 255)/256, 256>>>(gf, conv_w);

    conv1_kernel<<<dim3(160, 3, B_), 256>>>(x, conv_w, conv_b);

    gf_kernel<<<1, B_*GFC>>>(gf, out);

    cudaMemcpyAsync(out + OFF_H, prev_h, N_HC * sizeof(float),
                    cudaMemcpyDeviceToDevice);
    cudaMemcpyAsync(out + OFF_C, prev_c, N_HC * sizeof(float),
                    cudaMemcpyDeviceToDevice);

    conv2_kernel<<<dim3(160, 4, B_), 256>>>(prev_h, gates_w, gates_b);

    lstm_kernel<<<(unsigned)((N_HID/4 + 255)/256), 256>>>(prev_c, out);
}